// round 6
// baseline (speedup 1.0000x reference)
#include <cuda_runtime.h>
#include <cuda_bf16.h>
#include <cstdint>

#define BATCH 4
#define CDIM  768
#define TDIM  2048
#define NHEAD 12
#define HDIM  64
#define QKVROWS (3 * CDIM)

// ---------------------------------------------------------------------------
// Device scratch
// ---------------------------------------------------------------------------
__device__ float g_qkv[(size_t)BATCH * QKVROWS * TDIM];   // (B, 3C, T) tf32-rounded
__device__ float g_o  [(size_t)BATCH * CDIM    * TDIM];   // (B, C, T) tf32-rounded
__device__ float g_x  [(size_t)BATCH * CDIM    * TDIM];   // x, tf32-rounded
__device__ float g_wq [(size_t)QKVROWS * CDIM];           // Wqkv, tf32-rounded
__device__ float g_wo [(size_t)CDIM * CDIM];              // Wout, tf32-rounded

__device__ __forceinline__ uint32_t f2tf32(float x) {
    uint32_t r;
    asm("cvt.rna.tf32.f32 %0, %1;" : "=r"(r) : "f"(x));
    return r;
}

__device__ __forceinline__ float ex2_approx(float x) {
    float r;
    asm("ex2.approx.f32 %0, %1;" : "=f"(r) : "f"(x));
    return r;
}

__device__ __forceinline__ void mma_tf32(float* c, const uint32_t* a, const uint32_t* b) {
    asm volatile(
        "mma.sync.aligned.m16n8k8.row.col.f32.tf32.tf32.f32 "
        "{%0,%1,%2,%3}, {%4,%5,%6,%7}, {%8,%9}, {%0,%1,%2,%3};\n"
        : "+f"(c[0]), "+f"(c[1]), "+f"(c[2]), "+f"(c[3])
        : "r"(a[0]), "r"(a[1]), "r"(a[2]), "r"(a[3]), "r"(b[0]), "r"(b[1]));
}

__device__ __forceinline__ uint32_t smem_u32(const void* p) {
    return (uint32_t)__cvta_generic_to_shared(p);
}

__device__ __forceinline__ void cp_async16(uint32_t dst, const void* src) {
    asm volatile("cp.async.cg.shared.global [%0], [%1], 16;\n"
                 :: "r"(dst), "l"(src));
}
#define CP_COMMIT() asm volatile("cp.async.commit_group;\n")

// ---------------------------------------------------------------------------
// Pre-round: out[i] = tf32_rna(in[i]) as f32 bit pattern
// ---------------------------------------------------------------------------
__global__ __launch_bounds__(256)
void round_tf32_kernel(const float* __restrict__ in, float* __restrict__ out, int n)
{
    int i = (blockIdx.x * 256 + threadIdx.x) * 4;
    if (i < n) {
        float4 v = *reinterpret_cast<const float4*>(in + i);
        float4 o;
        o.x = __uint_as_float(f2tf32(v.x));
        o.y = __uint_as_float(f2tf32(v.y));
        o.z = __uint_as_float(f2tf32(v.z));
        o.w = __uint_as_float(f2tf32(v.w));
        *reinterpret_cast<float4*>(out + i) = o;
    }
}

// ---------------------------------------------------------------------------
// tf32 GEMM with cp.async double buffering (unchanged from R5 — at its
// mma.sync-from-smem ceiling).
// ---------------------------------------------------------------------------
#define GA_W (128 * 36)
#define GB_W (32 * 136)
#define GEMM_SMEM_BYTES ((2 * GA_W + 2 * GB_W) * 4)

template<bool ROUND_OUT>
__global__ __launch_bounds__(256, 2)
void gemm_tf32_cp(const float* __restrict__ A,
                  const float* __restrict__ Bmat,
                  const float* __restrict__ bias,
                  float* __restrict__ Cmat,
                  int M, int N, int K)
{
    extern __shared__ uint32_t gsm[];

    const float* Bp = Bmat + (size_t)blockIdx.z * (size_t)K * N;
    float*       Cp = Cmat + (size_t)blockIdx.z * (size_t)M * N;

    const int tid  = threadIdx.x;
    const int lane = tid & 31;
    const int warp = tid >> 5;
    const int g    = lane >> 2;
    const int tig  = lane & 3;
    const int wm   = warp >> 2;
    const int wn   = warp & 3;
    const int row0 = blockIdx.y * 128;
    const int col0 = blockIdx.x * 128;

    const int am  = tid >> 3;
    const int ak4 = (tid & 7) * 4;
    const int bk  = tid >> 5;
    const int bn4 = (tid & 31) * 4;

    const uint32_t sbase = smem_u32(gsm);

    float acc[4][4][4];
    #pragma unroll
    for (int i = 0; i < 4; i++)
        #pragma unroll
        for (int j = 0; j < 4; j++)
            #pragma unroll
            for (int r = 0; r < 4; r++) acc[i][j][r] = 0.0f;

    const int KT = K >> 5;

    auto issue = [&](int s) {
        const int k0 = s * 32;
        const uint32_t abase = sbase + (unsigned)((s & 1) * GA_W) * 4u;
        const uint32_t bbase = sbase + (unsigned)(2 * GA_W + (s & 1) * GB_W) * 4u;
        #pragma unroll
        for (int l = 0; l < 4; l++) {
            int m = am + 32 * l;
            cp_async16(abase + (unsigned)(m * 36 + ak4) * 4u,
                       A + (size_t)(row0 + m) * K + k0 + ak4);
        }
        #pragma unroll
        for (int l = 0; l < 4; l++) {
            int k = bk + 8 * l;
            cp_async16(bbase + (unsigned)(k * 136 + bn4) * 4u,
                       Bp + (size_t)(k0 + k) * N + col0 + bn4);
        }
        CP_COMMIT();
    };

    issue(0);
    if (KT > 1) issue(1);

    for (int kt = 0; kt < KT; kt++) {
        const int buf = kt & 1;
        if (kt + 1 < KT) asm volatile("cp.async.wait_group 1;\n");
        else             asm volatile("cp.async.wait_group 0;\n");
        __syncthreads();

        const uint32_t* Ab = gsm + buf * GA_W;
        const uint32_t* Bb = gsm + 2 * GA_W + buf * GB_W;

        #pragma unroll
        for (int kk = 0; kk < 32; kk += 8) {
            uint32_t af[4][4];
            uint32_t bf[4][2];
            #pragma unroll
            for (int mi = 0; mi < 4; mi++) {
                int m = wm * 64 + mi * 16 + g;
                af[mi][0] = Ab[m * 36 + kk + tig];
                af[mi][1] = Ab[(m + 8) * 36 + kk + tig];
                af[mi][2] = Ab[m * 36 + kk + tig + 4];
                af[mi][3] = Ab[(m + 8) * 36 + kk + tig + 4];
            }
            #pragma unroll
            for (int ni = 0; ni < 4; ni++) {
                int n = wn * 32 + ni * 8 + g;
                bf[ni][0] = Bb[(kk + tig) * 136 + n];
                bf[ni][1] = Bb[(kk + tig + 4) * 136 + n];
            }
            #pragma unroll
            for (int mi = 0; mi < 4; mi++)
                #pragma unroll
                for (int ni = 0; ni < 4; ni++)
                    mma_tf32(acc[mi][ni], af[mi], bf[ni]);
        }

        __syncthreads();
        if (kt + 2 < KT) issue(kt + 2);
    }

    #pragma unroll
    for (int mi = 0; mi < 4; mi++) {
        int r0 = row0 + wm * 64 + mi * 16 + g;
        float b0 = bias[r0];
        float b1 = bias[r0 + 8];
        #pragma unroll
        for (int ni = 0; ni < 4; ni++) {
            int cc = col0 + wn * 32 + ni * 8 + tig * 2;
            float o00 = acc[mi][ni][0] + b0, o01 = acc[mi][ni][1] + b0;
            float o10 = acc[mi][ni][2] + b1, o11 = acc[mi][ni][3] + b1;
            if (ROUND_OUT) {
                o00 = __uint_as_float(f2tf32(o00));
                o01 = __uint_as_float(f2tf32(o01));
                o10 = __uint_as_float(f2tf32(o10));
                o11 = __uint_as_float(f2tf32(o11));
            }
            *reinterpret_cast<float2*>(Cp + (size_t)r0 * N + cc)       = make_float2(o00, o01);
            *reinterpret_cast<float2*>(Cp + (size_t)(r0 + 8) * N + cc) = make_float2(o10, o11);
        }
    }
}

// ---------------------------------------------------------------------------
// Flash attention v6: 512 threads / 16 warps (4 per SMSP for pipe overlap),
// warp tile 16t x 64s / 16t x 64d, 3-stage cp.async K/V pipeline,
// ex2-folded softmax, register-resident P via quad shuffles.
// grid (T/256, H, B).
// ---------------------------------------------------------------------------
#define QS_P 65
#define KS_P 72
#define VS_P 68
#define FA_TBLK 256
#define KSTG (64 * KS_P)
#define VSTG (64 * VS_P)
#define FA_NCHUNK (TDIM / 64)
#define FA_SMEM_WORDS (FA_TBLK * QS_P + 3 * KSTG + 3 * VSTG + TDIM)
#define FA_SMEM_BYTES (FA_SMEM_WORDS * 4)
#define LOG2E 1.44269504088896340736f

__global__ __launch_bounds__(512, 1)
void flash_attn_v6(const int* __restrict__ mask)
{
    extern __shared__ uint32_t fsm[];
    uint32_t* Qs      = fsm;                       // [t][d] pitch 65
    uint32_t* Ks      = Qs + FA_TBLK * QS_P;       // 3 stages [d][s] pitch 72
    uint32_t* Vs      = Ks + 3 * KSTG;             // 3 stages [d][s] pitch 68
    float*    maskAll = (float*)(Vs + 3 * VSTG);   // 2048 biases (pre-scaled by log2e)

    const int b    = blockIdx.z;
    const int h    = blockIdx.y;
    const int tt   = blockIdx.x;
    const int tid  = threadIdx.x;
    const int lane = tid & 31;
    const int warp = tid >> 5;
    const int g    = lane >> 2;
    const int tig  = lane & 3;
    const int tw   = warp * 16;

    const size_t base = (size_t)b * QKVROWS * TDIM;
    const float* qptr = g_qkv + base + (size_t)(h * HDIM) * TDIM + tt * FA_TBLK;
    const float* kptr = g_qkv + base + (size_t)(CDIM + h * HDIM) * TDIM;
    const float* vptr = g_qkv + base + (size_t)(2 * CDIM + h * HDIM) * TDIM;

    const uint32_t kbase0 = smem_u32(Ks);
    const uint32_t vbase0 = smem_u32(Vs);

    auto issue = [&](int ch) {
        const uint32_t kb = kbase0 + (unsigned)((ch % 3) * KSTG) * 4u;
        const uint32_t vb = vbase0 + (unsigned)((ch % 3) * VSTG) * 4u;
        const int s0 = ch * 64;
        #pragma unroll
        for (int l = 0; l < 2; l++) {
            int lin = tid + l * 512;
            int d   = lin >> 4;
            int s4  = (lin & 15) * 4;
            cp_async16(kb + (unsigned)(d * KS_P + s4) * 4u,
                       kptr + (size_t)d * TDIM + s0 + s4);
            cp_async16(vb + (unsigned)(d * VS_P + s4) * 4u,
                       vptr + (size_t)d * TDIM + s0 + s4);
        }
        CP_COMMIT();
    };

    issue(0); issue(1); issue(2);

    // Stage Q tile (already tf32-rounded bits): Qs[t][d], transpose from [d][t]
    #pragma unroll
    for (int l = 0; l < 8; l++) {
        int lin = tid + l * 512;
        int d   = lin >> 6;
        int t4  = (lin & 63) * 4;
        float4 v = *reinterpret_cast<const float4*>(qptr + (size_t)d * TDIM + t4);
        Qs[(t4 + 0) * QS_P + d] = __float_as_uint(v.x);
        Qs[(t4 + 1) * QS_P + d] = __float_as_uint(v.y);
        Qs[(t4 + 2) * QS_P + d] = __float_as_uint(v.z);
        Qs[(t4 + 3) * QS_P + d] = __float_as_uint(v.w);
    }
    // Whole-row mask biases, pre-scaled by log2(e)
    for (int i = tid; i < TDIM; i += 512)
        maskAll[i] = (mask[(size_t)b * TDIM + i] == 0) ? (-10000.0f * LOG2E) : 0.0f;

    float accO[8][4];
    #pragma unroll
    for (int ni = 0; ni < 8; ni++)
        #pragma unroll
        for (int r = 0; r < 4; r++) accO[ni][r] = 0.0f;

    float rowl[2] = {0.0f, 0.0f};

    const float sc2 = 0.125f * LOG2E;   // folded scale: exp(s/8) = exp2(s*sc2)

    for (int kt = 0; kt < FA_NCHUNK; kt++) {
        if      (kt + 2 < FA_NCHUNK) asm volatile("cp.async.wait_group 2;\n");
        else if (kt + 1 < FA_NCHUNK) asm volatile("cp.async.wait_group 1;\n");
        else                         asm volatile("cp.async.wait_group 0;\n");
        __syncthreads();

        const uint32_t* Kb = Ks + (kt % 3) * KSTG;
        const uint32_t* Vb = Vs + (kt % 3) * VSTG;
        const float*    mb = maskAll + kt * 64;

        // ---- S = Q K^T, warp tile 16t x 64s ----
        float sacc[8][4];
        #pragma unroll
        for (int ni = 0; ni < 8; ni++)
            #pragma unroll
            for (int r = 0; r < 4; r++) sacc[ni][r] = 0.0f;

        #pragma unroll
        for (int kk = 0; kk < 8; kk++) {
            uint32_t af[4];
            {
                int t = tw + g;
                af[0] = Qs[t * QS_P + kk * 8 + tig];
                af[1] = Qs[(t + 8) * QS_P + kk * 8 + tig];
                af[2] = Qs[t * QS_P + kk * 8 + tig + 4];
                af[3] = Qs[(t + 8) * QS_P + kk * 8 + tig + 4];
            }
            uint32_t bf[8][2];
            #pragma unroll
            for (int ni = 0; ni < 8; ni++) {
                bf[ni][0] = Kb[(kk * 8 + tig) * KS_P + ni * 8 + g];
                bf[ni][1] = Kb[(kk * 8 + tig + 4) * KS_P + ni * 8 + g];
            }
            #pragma unroll
            for (int ni = 0; ni < 8; ni++)
                mma_tf32(sacc[ni], af, bf[ni]);
        }

        // ---- softmax numerators: p = ex2(s*sc2 + bias), P -> tf32 in place ----
        float rs[2] = {0.0f, 0.0f};
        #pragma unroll
        for (int ni = 0; ni < 8; ni++) {
            int sb = ni * 8 + tig * 2;
            float b0 = mb[sb], b1 = mb[sb + 1];
            float p0 = ex2_approx(fmaf(sacc[ni][0], sc2, b0));
            float p1 = ex2_approx(fmaf(sacc[ni][1], sc2, b1));
            float p2 = ex2_approx(fmaf(sacc[ni][2], sc2, b0));
            float p3 = ex2_approx(fmaf(sacc[ni][3], sc2, b1));
            rs[0] += p0 + p1;
            rs[1] += p2 + p3;
            sacc[ni][0] = __uint_as_float(f2tf32(p0));
            sacc[ni][1] = __uint_as_float(f2tf32(p1));
            sacc[ni][2] = __uint_as_float(f2tf32(p2));
            sacc[ni][3] = __uint_as_float(f2tf32(p3));
        }
        #pragma unroll
        for (int j = 0; j < 2; j++) {
            float r = rs[j];
            r += __shfl_xor_sync(0xffffffffu, r, 1);
            r += __shfl_xor_sync(0xffffffffu, r, 2);
            rowl[j] += r;
        }

        // ---- O += P V, P fragments via quad shuffles ----
        const int src0 = (lane & ~3) | (tig >> 1);
        const int src1 = src0 + 2;
        const bool podd = (tig & 1);
        #pragma unroll
        for (int kb = 0; kb < 8; kb++) {
            uint32_t bf[8][2];
            #pragma unroll
            for (int ni = 0; ni < 8; ni++) {
                bf[ni][0] = Vb[(ni * 8 + g) * VS_P + kb * 8 + tig];
                bf[ni][1] = Vb[(ni * 8 + g) * VS_P + kb * 8 + tig + 4];
            }
            float t00 = __shfl_sync(0xffffffffu, sacc[kb][0], src0);
            float t01 = __shfl_sync(0xffffffffu, sacc[kb][1], src0);
            float t02 = __shfl_sync(0xffffffffu, sacc[kb][2], src0);
            float t03 = __shfl_sync(0xffffffffu, sacc[kb][3], src0);
            float t10 = __shfl_sync(0xffffffffu, sacc[kb][0], src1);
            float t11 = __shfl_sync(0xffffffffu, sacc[kb][1], src1);
            float t12 = __shfl_sync(0xffffffffu, sacc[kb][2], src1);
            float t13 = __shfl_sync(0xffffffffu, sacc[kb][3], src1);
            uint32_t a[4];
            a[0] = __float_as_uint(podd ? t01 : t00);
            a[1] = __float_as_uint(podd ? t03 : t02);
            a[2] = __float_as_uint(podd ? t11 : t10);
            a[3] = __float_as_uint(podd ? t13 : t12);
            #pragma unroll
            for (int ni = 0; ni < 8; ni++)
                mma_tf32(accO[ni], a, bf[ni]);
        }

        __syncthreads();
        if (kt + 3 < FA_NCHUNK) issue(kt + 3);
    }

    // ---- epilogue: normalize, round to tf32 bits (GEMM3 eats raw) ----
    float* optr = g_o + (size_t)b * CDIM * TDIM + (size_t)(h * HDIM) * TDIM
                + tt * FA_TBLK + tw;
    float il0 = 1.0f / rowl[0];
    float il1 = 1.0f / rowl[1];
    #pragma unroll
    for (int ni = 0; ni < 8; ni++) {
        int d = ni * 8 + tig * 2;
        float* op = optr + (size_t)d * TDIM + g;
        op[0]        = __uint_as_float(f2tf32(accO[ni][0] * il0));
        op[TDIM]     = __uint_as_float(f2tf32(accO[ni][1] * il0));
        op[8]        = __uint_as_float(f2tf32(accO[ni][2] * il1));
        op[TDIM + 8] = __uint_as_float(f2tf32(accO[ni][3] * il1));
    }
}

// ---------------------------------------------------------------------------
// kernel_launch
// ---------------------------------------------------------------------------
extern "C" void kernel_launch(void* const* d_in, const int* in_sizes, int n_in,
                              void* d_out, int out_size)
{
    const float* x    = (const float*)d_in[0];
    const int*   mask = (const int*)  d_in[1];
    const float* Wqkv = (const float*)d_in[2];
    const float* bqkv = (const float*)d_in[3];
    const float* Wout = (const float*)d_in[4];
    const float* bout = (const float*)d_in[5];
    float*       out  = (float*)d_out;

    float *qkv_p, *o_p, *x_p, *wq_p, *wo_p;
    cudaGetSymbolAddress((void**)&qkv_p, g_qkv);
    cudaGetSymbolAddress((void**)&o_p,   g_o);
    cudaGetSymbolAddress((void**)&x_p,   g_x);
    cudaGetSymbolAddress((void**)&wq_p,  g_wq);
    cudaGetSymbolAddress((void**)&wo_p,  g_wo);

    cudaFuncSetAttribute(gemm_tf32_cp<true>,
                         cudaFuncAttributeMaxDynamicSharedMemorySize, GEMM_SMEM_BYTES);
    cudaFuncSetAttribute(gemm_tf32_cp<false>,
                         cudaFuncAttributeMaxDynamicSharedMemorySize, GEMM_SMEM_BYTES);
    cudaFuncSetAttribute(flash_attn_v6,
                         cudaFuncAttributeMaxDynamicSharedMemorySize, FA_SMEM_BYTES);

    // 0) pre-round inputs to tf32 bit patterns
    {
        const int nx = BATCH * CDIM * TDIM;
        const int nq = QKVROWS * CDIM;
        const int nw = CDIM * CDIM;
        round_tf32_kernel<<<nx / 1024, 256>>>(x,    x_p,  nx);
        round_tf32_kernel<<<nq / 1024, 256>>>(Wqkv, wq_p, nq);
        round_tf32_kernel<<<nw / 1024, 256>>>(Wout, wo_p, nw);
    }

    // 1) qkv = Wqkv @ x + bqkv  (output rounded to tf32 bits for flash)
    {
        dim3 grid(TDIM / 128, QKVROWS / 128, BATCH);
        gemm_tf32_cp<true><<<grid, 256, GEMM_SMEM_BYTES>>>(wq_p, x_p, bqkv, qkv_p,
                                                           QKVROWS, TDIM, CDIM);
    }
    // 2) fused flash attention
    {
        dim3 grid(TDIM / FA_TBLK, NHEAD, BATCH);
        flash_attn_v6<<<grid, 512, FA_SMEM_BYTES>>>(mask);
    }
    // 3) out = Wout @ o + bout  (full f32 output)
    {
        dim3 grid(TDIM / 128, CDIM / 128, BATCH);
        gemm_tf32_cp<false><<<grid, 256, GEMM_SMEM_BYTES>>>(wo_p, o_p, bout, out,
                                                            CDIM, TDIM, CDIM);
    }
}

// round 7
// speedup vs baseline: 1.2227x; 1.2227x over previous
#include <cuda_runtime.h>
#include <cuda_bf16.h>
#include <cstdint>

#define BATCH 4
#define CDIM  768
#define TDIM  2048
#define NHEAD 12
#define HDIM  64
#define QKVROWS (3 * CDIM)

// ---------------------------------------------------------------------------
// Device scratch
// ---------------------------------------------------------------------------
__device__ float g_qkv[(size_t)BATCH * QKVROWS * TDIM];   // (B, 3C, T) tf32-rounded
__device__ float g_o  [(size_t)BATCH * CDIM    * TDIM];   // (B, C, T) tf32-rounded
__device__ float g_x  [(size_t)BATCH * CDIM    * TDIM];   // x, tf32-rounded
__device__ float g_wq [(size_t)QKVROWS * CDIM];           // Wqkv, tf32-rounded
__device__ float g_wo [(size_t)CDIM * CDIM];              // Wout, tf32-rounded

__device__ __forceinline__ uint32_t f2tf32(float x) {
    uint32_t r;
    asm("cvt.rna.tf32.f32 %0, %1;" : "=r"(r) : "f"(x));
    return r;
}

__device__ __forceinline__ float ex2_approx(float x) {
    float r;
    asm("ex2.approx.f32 %0, %1;" : "=f"(r) : "f"(x));
    return r;
}

__device__ __forceinline__ void mma_tf32(float* c, const uint32_t* a, const uint32_t* b) {
    asm volatile(
        "mma.sync.aligned.m16n8k8.row.col.f32.tf32.tf32.f32 "
        "{%0,%1,%2,%3}, {%4,%5,%6,%7}, {%8,%9}, {%0,%1,%2,%3};\n"
        : "+f"(c[0]), "+f"(c[1]), "+f"(c[2]), "+f"(c[3])
        : "r"(a[0]), "r"(a[1]), "r"(a[2]), "r"(a[3]), "r"(b[0]), "r"(b[1]));
}

__device__ __forceinline__ uint32_t smem_u32(const void* p) {
    return (uint32_t)__cvta_generic_to_shared(p);
}

__device__ __forceinline__ void cp_async16(uint32_t dst, const void* src) {
    asm volatile("cp.async.cg.shared.global [%0], [%1], 16;\n"
                 :: "r"(dst), "l"(src));
}
#define CP_COMMIT() asm volatile("cp.async.commit_group;\n")

// ---------------------------------------------------------------------------
// Pre-round: out[i] = tf32_rna(in[i]) as f32 bit pattern
// ---------------------------------------------------------------------------
__global__ __launch_bounds__(256)
void round_tf32_kernel(const float* __restrict__ in, float* __restrict__ out, int n)
{
    int i = (blockIdx.x * 256 + threadIdx.x) * 4;
    if (i < n) {
        float4 v = *reinterpret_cast<const float4*>(in + i);
        float4 o;
        o.x = __uint_as_float(f2tf32(v.x));
        o.y = __uint_as_float(f2tf32(v.y));
        o.z = __uint_as_float(f2tf32(v.z));
        o.w = __uint_as_float(f2tf32(v.w));
        *reinterpret_cast<float4*>(out + i) = o;
    }
}

// ---------------------------------------------------------------------------
// tf32 GEMM with cp.async double buffering (unchanged — at its
// mma.sync-from-smem ceiling).
// ---------------------------------------------------------------------------
#define GA_W (128 * 36)
#define GB_W (32 * 136)
#define GEMM_SMEM_BYTES ((2 * GA_W + 2 * GB_W) * 4)

template<bool ROUND_OUT>
__global__ __launch_bounds__(256, 2)
void gemm_tf32_cp(const float* __restrict__ A,
                  const float* __restrict__ Bmat,
                  const float* __restrict__ bias,
                  float* __restrict__ Cmat,
                  int M, int N, int K)
{
    extern __shared__ uint32_t gsm[];

    const float* Bp = Bmat + (size_t)blockIdx.z * (size_t)K * N;
    float*       Cp = Cmat + (size_t)blockIdx.z * (size_t)M * N;

    const int tid  = threadIdx.x;
    const int lane = tid & 31;
    const int warp = tid >> 5;
    const int g    = lane >> 2;
    const int tig  = lane & 3;
    const int wm   = warp >> 2;
    const int wn   = warp & 3;
    const int row0 = blockIdx.y * 128;
    const int col0 = blockIdx.x * 128;

    const int am  = tid >> 3;
    const int ak4 = (tid & 7) * 4;
    const int bk  = tid >> 5;
    const int bn4 = (tid & 31) * 4;

    const uint32_t sbase = smem_u32(gsm);

    float acc[4][4][4];
    #pragma unroll
    for (int i = 0; i < 4; i++)
        #pragma unroll
        for (int j = 0; j < 4; j++)
            #pragma unroll
            for (int r = 0; r < 4; r++) acc[i][j][r] = 0.0f;

    const int KT = K >> 5;

    auto issue = [&](int s) {
        const int k0 = s * 32;
        const uint32_t abase = sbase + (unsigned)((s & 1) * GA_W) * 4u;
        const uint32_t bbase = sbase + (unsigned)(2 * GA_W + (s & 1) * GB_W) * 4u;
        #pragma unroll
        for (int l = 0; l < 4; l++) {
            int m = am + 32 * l;
            cp_async16(abase + (unsigned)(m * 36 + ak4) * 4u,
                       A + (size_t)(row0 + m) * K + k0 + ak4);
        }
        #pragma unroll
        for (int l = 0; l < 4; l++) {
            int k = bk + 8 * l;
            cp_async16(bbase + (unsigned)(k * 136 + bn4) * 4u,
                       Bp + (size_t)(k0 + k) * N + col0 + bn4);
        }
        CP_COMMIT();
    };

    issue(0);
    if (KT > 1) issue(1);

    for (int kt = 0; kt < KT; kt++) {
        const int buf = kt & 1;
        if (kt + 1 < KT) asm volatile("cp.async.wait_group 1;\n");
        else             asm volatile("cp.async.wait_group 0;\n");
        __syncthreads();

        const uint32_t* Ab = gsm + buf * GA_W;
        const uint32_t* Bb = gsm + 2 * GA_W + buf * GB_W;

        #pragma unroll
        for (int kk = 0; kk < 32; kk += 8) {
            uint32_t af[4][4];
            uint32_t bf[4][2];
            #pragma unroll
            for (int mi = 0; mi < 4; mi++) {
                int m = wm * 64 + mi * 16 + g;
                af[mi][0] = Ab[m * 36 + kk + tig];
                af[mi][1] = Ab[(m + 8) * 36 + kk + tig];
                af[mi][2] = Ab[m * 36 + kk + tig + 4];
                af[mi][3] = Ab[(m + 8) * 36 + kk + tig + 4];
            }
            #pragma unroll
            for (int ni = 0; ni < 4; ni++) {
                int n = wn * 32 + ni * 8 + g;
                bf[ni][0] = Bb[(kk + tig) * 136 + n];
                bf[ni][1] = Bb[(kk + tig + 4) * 136 + n];
            }
            #pragma unroll
            for (int mi = 0; mi < 4; mi++)
                #pragma unroll
                for (int ni = 0; ni < 4; ni++)
                    mma_tf32(acc[mi][ni], af[mi], bf[ni]);
        }

        __syncthreads();
        if (kt + 2 < KT) issue(kt + 2);
    }

    #pragma unroll
    for (int mi = 0; mi < 4; mi++) {
        int r0 = row0 + wm * 64 + mi * 16 + g;
        float b0 = bias[r0];
        float b1 = bias[r0 + 8];
        #pragma unroll
        for (int ni = 0; ni < 4; ni++) {
            int cc = col0 + wn * 32 + ni * 8 + tig * 2;
            float o00 = acc[mi][ni][0] + b0, o01 = acc[mi][ni][1] + b0;
            float o10 = acc[mi][ni][2] + b1, o11 = acc[mi][ni][3] + b1;
            if (ROUND_OUT) {
                o00 = __uint_as_float(f2tf32(o00));
                o01 = __uint_as_float(f2tf32(o01));
                o10 = __uint_as_float(f2tf32(o10));
                o11 = __uint_as_float(f2tf32(o11));
            }
            *reinterpret_cast<float2*>(Cp + (size_t)r0 * N + cc)       = make_float2(o00, o01);
            *reinterpret_cast<float2*>(Cp + (size_t)(r0 + 8) * N + cc) = make_float2(o10, o11);
        }
    }
}

// ---------------------------------------------------------------------------
// Flash attention v7 (= v5 structure, issue-slimmed):
//  - 256 threads / 8 warps, warp tile 32t x 64s / 32t x 64d (crossbar-safe)
//  - Q fragments hoisted into registers ONCE per block (chunk-invariant)
//  - no cvt on P: mma hardware truncates f32 -> tf32
//  - 3-stage cp.async K/V ring, whole-row mask bias, ex2-folded softmax
// grid (T/256, H, B).
// ---------------------------------------------------------------------------
#define KS_P 72
#define VS_P 68
#define FA_TBLK 256
#define KSTG (64 * KS_P)
#define VSTG (64 * VS_P)
#define FA_NCHUNK (TDIM / 64)
#define FA_SMEM_WORDS (3 * KSTG + 3 * VSTG + TDIM)
#define FA_SMEM_BYTES (FA_SMEM_WORDS * 4)
#define LOG2E 1.44269504088896340736f

__global__ __launch_bounds__(256, 1)
void flash_attn_v7(const int* __restrict__ mask)
{
    extern __shared__ uint32_t fsm[];
    uint32_t* Ks      = fsm;                       // 3 stages [d][s] pitch 72
    uint32_t* Vs      = Ks + 3 * KSTG;             // 3 stages [d][s] pitch 68
    float*    maskAll = (float*)(Vs + 3 * VSTG);   // 2048 biases (pre-scaled by log2e)

    const int b    = blockIdx.z;
    const int h    = blockIdx.y;
    const int tt   = blockIdx.x;
    const int tid  = threadIdx.x;
    const int lane = tid & 31;
    const int warp = tid >> 5;
    const int g    = lane >> 2;
    const int tig  = lane & 3;
    const int tw   = warp * 32;

    const size_t base = (size_t)b * QKVROWS * TDIM;
    const float* qptr = g_qkv + base + (size_t)(h * HDIM) * TDIM + tt * FA_TBLK + tw;
    const float* kptr = g_qkv + base + (size_t)(CDIM + h * HDIM) * TDIM;
    const float* vptr = g_qkv + base + (size_t)(2 * CDIM + h * HDIM) * TDIM;

    const uint32_t kbase0 = smem_u32(Ks);
    const uint32_t vbase0 = smem_u32(Vs);

    auto issue = [&](int ch) {
        const uint32_t kb = kbase0 + (unsigned)((ch % 3) * KSTG) * 4u;
        const uint32_t vb = vbase0 + (unsigned)((ch % 3) * VSTG) * 4u;
        const int s0 = ch * 64;
        #pragma unroll
        for (int l = 0; l < 4; l++) {
            int lin = tid + l * 256;
            int d   = lin >> 4;
            int s4  = (lin & 15) * 4;
            cp_async16(kb + (unsigned)(d * KS_P + s4) * 4u,
                       kptr + (size_t)d * TDIM + s0 + s4);
            cp_async16(vb + (unsigned)(d * VS_P + s4) * 4u,
                       vptr + (size_t)d * TDIM + s0 + s4);
        }
        CP_COMMIT();
    };

    issue(0); issue(1); issue(2);

    // Q fragments in registers, loaded once (g_qkv already tf32-rounded bits).
    // Layout verified in R3: a[0]=(m=g,k=tig), a[1]=(m=g+8,k=tig),
    // a[2]=(m=g,k=tig+4), a[3]=(m=g+8,k=tig+4); m=t index, k=d index.
    uint32_t Qf[2][8][4];
    #pragma unroll
    for (int mi = 0; mi < 2; mi++)
        #pragma unroll
        for (int kk = 0; kk < 8; kk++) {
            const float* qp = qptr + (size_t)(kk * 8 + tig) * TDIM + mi * 16 + g;
            Qf[mi][kk][0] = __float_as_uint(qp[0]);
            Qf[mi][kk][1] = __float_as_uint(qp[8]);
            Qf[mi][kk][2] = __float_as_uint(qp[4 * TDIM]);
            Qf[mi][kk][3] = __float_as_uint(qp[4 * TDIM + 8]);
        }

    // Whole-row mask biases, pre-scaled by log2(e)
    for (int i = tid; i < TDIM; i += 256)
        maskAll[i] = (mask[(size_t)b * TDIM + i] == 0) ? (-10000.0f * LOG2E) : 0.0f;

    float accO[2][8][4];
    #pragma unroll
    for (int mi = 0; mi < 2; mi++)
        #pragma unroll
        for (int ni = 0; ni < 8; ni++)
            #pragma unroll
            for (int r = 0; r < 4; r++) accO[mi][ni][r] = 0.0f;

    float rowl[2][2] = {{0.0f, 0.0f}, {0.0f, 0.0f}};

    const float sc2 = 0.125f * LOG2E;   // exp(s/8) = exp2(s*sc2)

    for (int kt = 0; kt < FA_NCHUNK; kt++) {
        if      (kt + 2 < FA_NCHUNK) asm volatile("cp.async.wait_group 2;\n");
        else if (kt + 1 < FA_NCHUNK) asm volatile("cp.async.wait_group 1;\n");
        else                         asm volatile("cp.async.wait_group 0;\n");
        __syncthreads();

        const uint32_t* Kb = Ks + (kt % 3) * KSTG;
        const uint32_t* Vb = Vs + (kt % 3) * VSTG;
        const float*    mb = maskAll + kt * 64;

        // ---- S = Q K^T, warp tile 32t x 64s ----
        float sacc[2][8][4];
        #pragma unroll
        for (int mi = 0; mi < 2; mi++)
            #pragma unroll
            for (int ni = 0; ni < 8; ni++)
                #pragma unroll
                for (int r = 0; r < 4; r++) sacc[mi][ni][r] = 0.0f;

        #pragma unroll
        for (int kk = 0; kk < 8; kk++) {
            uint32_t bf[8][2];
            #pragma unroll
            for (int ni = 0; ni < 8; ni++) {
                bf[ni][0] = Kb[(kk * 8 + tig) * KS_P + ni * 8 + g];
                bf[ni][1] = Kb[(kk * 8 + tig + 4) * KS_P + ni * 8 + g];
            }
            #pragma unroll
            for (int mi = 0; mi < 2; mi++)
                #pragma unroll
                for (int ni = 0; ni < 8; ni++)
                    mma_tf32(sacc[mi][ni], Qf[mi][kk], bf[ni]);
        }

        // ---- softmax numerators: p = ex2(s*sc2 + bias); P stays raw f32
        //      (mma truncates f32 -> tf32 in hardware) ----
        float rs[2][2] = {{0.0f, 0.0f}, {0.0f, 0.0f}};
        #pragma unroll
        for (int mi = 0; mi < 2; mi++)
            #pragma unroll
            for (int ni = 0; ni < 8; ni++) {
                int sb = ni * 8 + tig * 2;
                float b0 = mb[sb], b1 = mb[sb + 1];
                float p0 = ex2_approx(fmaf(sacc[mi][ni][0], sc2, b0));
                float p1 = ex2_approx(fmaf(sacc[mi][ni][1], sc2, b1));
                float p2 = ex2_approx(fmaf(sacc[mi][ni][2], sc2, b0));
                float p3 = ex2_approx(fmaf(sacc[mi][ni][3], sc2, b1));
                rs[mi][0] += p0 + p1;
                rs[mi][1] += p2 + p3;
                sacc[mi][ni][0] = p0;
                sacc[mi][ni][1] = p1;
                sacc[mi][ni][2] = p2;
                sacc[mi][ni][3] = p3;
            }
        #pragma unroll
        for (int mi = 0; mi < 2; mi++)
            #pragma unroll
            for (int j = 0; j < 2; j++) {
                float r = rs[mi][j];
                r += __shfl_xor_sync(0xffffffffu, r, 1);
                r += __shfl_xor_sync(0xffffffffu, r, 2);
                rowl[mi][j] += r;
            }

        // ---- O += P V, P fragments via quad shuffles ----
        const int src0 = (lane & ~3) | (tig >> 1);
        const int src1 = src0 + 2;
        const bool podd = (tig & 1);
        #pragma unroll
        for (int kb = 0; kb < 8; kb++) {
            uint32_t bf[8][2];
            #pragma unroll
            for (int ni = 0; ni < 8; ni++) {
                bf[ni][0] = Vb[(ni * 8 + g) * VS_P + kb * 8 + tig];
                bf[ni][1] = Vb[(ni * 8 + g) * VS_P + kb * 8 + tig + 4];
            }
            #pragma unroll
            for (int mi = 0; mi < 2; mi++) {
                float t00 = __shfl_sync(0xffffffffu, sacc[mi][kb][0], src0);
                float t01 = __shfl_sync(0xffffffffu, sacc[mi][kb][1], src0);
                float t02 = __shfl_sync(0xffffffffu, sacc[mi][kb][2], src0);
                float t03 = __shfl_sync(0xffffffffu, sacc[mi][kb][3], src0);
                float t10 = __shfl_sync(0xffffffffu, sacc[mi][kb][0], src1);
                float t11 = __shfl_sync(0xffffffffu, sacc[mi][kb][1], src1);
                float t12 = __shfl_sync(0xffffffffu, sacc[mi][kb][2], src1);
                float t13 = __shfl_sync(0xffffffffu, sacc[mi][kb][3], src1);
                uint32_t a[4];
                a[0] = __float_as_uint(podd ? t01 : t00);
                a[1] = __float_as_uint(podd ? t03 : t02);
                a[2] = __float_as_uint(podd ? t11 : t10);
                a[3] = __float_as_uint(podd ? t13 : t12);
                #pragma unroll
                for (int ni = 0; ni < 8; ni++)
                    mma_tf32(accO[mi][ni], a, bf[ni]);
            }
        }

        __syncthreads();
        if (kt + 3 < FA_NCHUNK) issue(kt + 3);
    }

    // ---- epilogue: normalize, round to tf32 bits (GEMM3 eats raw) ----
    float* optr = g_o + (size_t)b * CDIM * TDIM + (size_t)(h * HDIM) * TDIM
                + tt * FA_TBLK + tw;
    #pragma unroll
    for (int mi = 0; mi < 2; mi++) {
        float il0 = 1.0f / rowl[mi][0];
        float il1 = 1.0f / rowl[mi][1];
        #pragma unroll
        for (int ni = 0; ni < 8; ni++) {
            int d = ni * 8 + tig * 2;
            float* op = optr + (size_t)d * TDIM + mi * 16 + g;
            op[0]        = __uint_as_float(f2tf32(accO[mi][ni][0] * il0));
            op[TDIM]     = __uint_as_float(f2tf32(accO[mi][ni][1] * il0));
            op[8]        = __uint_as_float(f2tf32(accO[mi][ni][2] * il1));
            op[TDIM + 8] = __uint_as_float(f2tf32(accO[mi][ni][3] * il1));
        }
    }
}

// ---------------------------------------------------------------------------
// kernel_launch
// ---------------------------------------------------------------------------
extern "C" void kernel_launch(void* const* d_in, const int* in_sizes, int n_in,
                              void* d_out, int out_size)
{
    const float* x    = (const float*)d_in[0];
    const int*   mask = (const int*)  d_in[1];
    const float* Wqkv = (const float*)d_in[2];
    const float* bqkv = (const float*)d_in[3];
    const float* Wout = (const float*)d_in[4];
    const float* bout = (const float*)d_in[5];
    float*       out  = (float*)d_out;

    float *qkv_p, *o_p, *x_p, *wq_p, *wo_p;
    cudaGetSymbolAddress((void**)&qkv_p, g_qkv);
    cudaGetSymbolAddress((void**)&o_p,   g_o);
    cudaGetSymbolAddress((void**)&x_p,   g_x);
    cudaGetSymbolAddress((void**)&wq_p,  g_wq);
    cudaGetSymbolAddress((void**)&wo_p,  g_wo);

    cudaFuncSetAttribute(gemm_tf32_cp<true>,
                         cudaFuncAttributeMaxDynamicSharedMemorySize, GEMM_SMEM_BYTES);
    cudaFuncSetAttribute(gemm_tf32_cp<false>,
                         cudaFuncAttributeMaxDynamicSharedMemorySize, GEMM_SMEM_BYTES);
    cudaFuncSetAttribute(flash_attn_v7,
                         cudaFuncAttributeMaxDynamicSharedMemorySize, FA_SMEM_BYTES);

    // 0) pre-round inputs to tf32 bit patterns
    {
        const int nx = BATCH * CDIM * TDIM;
        const int nq = QKVROWS * CDIM;
        const int nw = CDIM * CDIM;
        round_tf32_kernel<<<nx / 1024, 256>>>(x,    x_p,  nx);
        round_tf32_kernel<<<nq / 1024, 256>>>(Wqkv, wq_p, nq);
        round_tf32_kernel<<<nw / 1024, 256>>>(Wout, wo_p, nw);
    }

    // 1) qkv = Wqkv @ x + bqkv  (output rounded to tf32 bits for flash)
    {
        dim3 grid(TDIM / 128, QKVROWS / 128, BATCH);
        gemm_tf32_cp<true><<<grid, 256, GEMM_SMEM_BYTES>>>(wq_p, x_p, bqkv, qkv_p,
                                                           QKVROWS, TDIM, CDIM);
    }
    // 2) fused flash attention
    {
        dim3 grid(TDIM / FA_TBLK, NHEAD, BATCH);
        flash_attn_v7<<<grid, 256, FA_SMEM_BYTES>>>(mask);
    }
    // 3) out = Wout @ o + bout  (full f32 output)
    {
        dim3 grid(TDIM / 128, CDIM / 128, BATCH);
        gemm_tf32_cp<false><<<grid, 256, GEMM_SMEM_BYTES>>>(wo_p, o_p, bout, out,
                                                            CDIM, TDIM, CDIM);
    }
}